// round 17
// baseline (speedup 1.0000x reference)
#include <cuda_runtime.h>
#include <cuda_fp16.h>
#include <cstdint>

// Problem constants (shapes fixed by the dataset)
#define MAX_NODES 50000
#define F_IN   32
#define F_OUT  32
#define NB     4
#define K16    (NB * NB)          // 16 basis products
#define YROW   (K16 * F_OUT)      // 512 values per node (j = kx*128 + ky*32 + ch)

// Scratch: Y[n, j] = sum_i x_j[n,i] * W[j>>5, i, j&31]  in fp16 (51.2 MB)
__device__ __half g_Y[(size_t)MAX_NODES * YROW];

struct alignas(8) Half4 { __half2 a, b; };

// ---------------------------------------------------------------------------
// Kernel 1: Y = X @ Wbig via HMMA m16n8k16 (fp16 in, fp32 acc).
//   Wbig[i, j] = w[j>>5][i][j&31]  ->  one GEMM [N,32] x [32,512].
// Round-8 structure exactly (measured best across 5 variants); the output
// zero-fill has been moved to a cudaMemsetAsync so K1 starts W-stage + MMA
// work immediately. 256 threads = 8 warps; each warp owns a 16-node m-tile,
// sweeps 64 n-tiles in 2 phases of 32. D fragments staged in a per-warp smem
// tile, flushed with coalesced 512B row stores.
// ---------------------------------------------------------------------------
#define WPAD  40    // halves per Ws row (80 B stride: ldmatrix conflict-free)
#define DCOLS 264   // 256 data halves + 8 pad (row stride 528 B, conflict-free)

__global__ __launch_bounds__(256, 2) void build_Y_mma(
    const float* __restrict__ x,     // [N, 32] fp32
    const float* __restrict__ w,     // [16, 32, 32] fp32
    int n_nodes)
{
    extern __shared__ __half smem[];
    __half* Ws = smem;                                 // 512*WPAD = 40 KB
    __half* Dw = smem + 512 * WPAD +
                 (threadIdx.x >> 5) * (16 * DCOLS);    // per-warp 16x264 tile

    // Stage WbigT[j][i] = w[k][i][o],  j = k*32 + o  (coalesced global reads)
    for (int idx = threadIdx.x; idx < K16 * F_IN * F_OUT; idx += blockDim.x) {
        int k = idx >> 10, i = (idx >> 5) & 31, o = idx & 31;
        Ws[(k * 32 + o) * WPAD + i] = __float2half_rn(w[idx]);
    }
    __syncthreads();

    const int lane = threadIdx.x & 31;

    // ldmatrix.x2 source addresses for B (lanes 0-7: mat0, 8-15: mat1)
    const unsigned bbase = (unsigned)__cvta_generic_to_shared(Ws);
    const int brow  = lane & 7;          // row within n-tile
    const int bhalf = (lane >> 3) & 1;   // mat1 -> k columns +8

    const int mtiles = n_nodes >> 4;     // N divisible by 16 (50000)
    const int warp_gl = blockIdx.x * 8 + (threadIdx.x >> 5);

    for (int mt = warp_gl; mt < mtiles; mt += gridDim.x * 8) {
        const int n0 = mt << 4;

        // A fragments: 2 k-chunks x 4 pairs, straight from global fp32.
        // pair p: row = n0 + l/4 + 8*(p&1), col = kc*16 + (l%4)*2 + 8*(p>>1)
        uint32_t afr[2][4];
        const int ar = n0 + (lane >> 2);
        const int ac = (lane & 3) * 2;
        #pragma unroll
        for (int kc = 0; kc < 2; kc++)
            #pragma unroll
            for (int p = 0; p < 4; p++) {
                int r = ar + ((p & 1) << 3);
                int cc = kc * 16 + ac + ((p >> 1) << 3);
                float2 v = *(const float2*)&x[r * F_IN + cc];
                __half2 h = __floats2half2_rn(v.x, v.y);
                afr[kc][p] = *(uint32_t*)&h;
            }

        __half* d_lo = &Dw[(lane >> 2) * DCOLS + ac];       // row l/4
        __half* d_hi = &Dw[((lane >> 2) + 8) * DCOLS + ac]; // row l/4 + 8

        #pragma unroll
        for (int ph = 0; ph < 2; ph++) {
            #pragma unroll 4
            for (int ntl = 0; ntl < 32; ntl++) {
                const int nt = ph * 32 + ntl;
                unsigned s0 = bbase +
                    (((nt * 8 + brow) * WPAD) + bhalf * 8) * 2u;
                uint32_t b00, b01, b10, b11;
                asm volatile("ldmatrix.sync.aligned.m8n8.x2.shared.b16 {%0,%1}, [%2];"
                             : "=r"(b00), "=r"(b01) : "r"(s0));
                asm volatile("ldmatrix.sync.aligned.m8n8.x2.shared.b16 {%0,%1}, [%2];"
                             : "=r"(b10), "=r"(b11) : "r"(s0 + 32u));

                float d0 = 0.f, d1 = 0.f, d2 = 0.f, d3 = 0.f;
                asm volatile(
                    "mma.sync.aligned.m16n8k16.row.col.f32.f16.f16.f32 "
                    "{%0,%1,%2,%3}, {%4,%5,%6,%7}, {%8,%9}, {%0,%1,%2,%3};"
                    : "+f"(d0), "+f"(d1), "+f"(d2), "+f"(d3)
                    : "r"(afr[0][0]), "r"(afr[0][1]), "r"(afr[0][2]), "r"(afr[0][3]),
                      "r"(b00), "r"(b01));
                asm volatile(
                    "mma.sync.aligned.m16n8k16.row.col.f32.f16.f16.f32 "
                    "{%0,%1,%2,%3}, {%4,%5,%6,%7}, {%8,%9}, {%0,%1,%2,%3};"
                    : "+f"(d0), "+f"(d1), "+f"(d2), "+f"(d3)
                    : "r"(afr[1][0]), "r"(afr[1][1]), "r"(afr[1][2]), "r"(afr[1][3]),
                      "r"(b10), "r"(b11));

                // Stage D in smem (conflict-free STS.32)
                *(__half2*)&d_lo[ntl * 8] = __floats2half2_rn(d0, d1);
                *(__half2*)&d_hi[ntl * 8] = __floats2half2_rn(d2, d3);
            }
            __syncwarp();

            // Coalesced flush: 16 rows x 512 B; one row per STG.128 instr
            #pragma unroll
            for (int it = 0; it < 16; it++) {
                int i = it * 32 + lane;
                int r = i >> 5, c = i & 31;
                *(int4*)&g_Y[(size_t)(n0 + r) * YROW + ph * 256 + c * 8] =
                    *(const int4*)&Dw[r * DCOLS + c * 8];
            }
            __syncwarp();
        }
    }
}

// ---------------------------------------------------------------------------
// Kernel 2: bilinear gather from fp16 Y + vectorized fp32 reduction scatter.
// Measured-best operating point (round 11): 8 threads/edge, 4x LDG.64 corner
// loads, one RED.v4 per thread, TWO edges per thread (e and e + E/2) for MLP.
// ---------------------------------------------------------------------------
__global__ __launch_bounds__(256) void edge_msg_kernel(
    const int*    __restrict__ ei,   // [2, E] : row0 = dst, row1 = src
    const float2* __restrict__ ea,   // [E]
    float*        __restrict__ out,  // [N, 32]
    int E, int Ehalf)
{
    const int t = blockIdx.x * blockDim.x + threadIdx.x;
    const int e0 = t >> 3;           // 8 threads per edge
    const int c = (t & 7) << 2;      // base of this thread's 4 outputs
    if (e0 >= Ehalf) return;
    const int e1 = e0 + Ehalf;
    const bool has1 = (e1 < E);

    // ---- gather both edges' metadata (independent loads) ----
    const int dst0 = __ldg(&ei[e0]);
    const int src0 = __ldg(&ei[E + e0]);
    const float2 a0 = __ldg(&ea[e0]);
    const int dst1 = has1 ? __ldg(&ei[e1]) : 0;
    const int src1 = has1 ? __ldg(&ei[E + e1]) : 0;
    const float2 a1 = has1 ? __ldg(&ea[e1]) : make_float2(0.f, 0.f);

    // ---- coefficients edge 0 ----
    float ux0 = fminf(fmaxf((a0.x + 1.0f) * 1.5f, 0.0f), 3.0f);
    float uy0 = fminf(fmaxf((a0.y + 1.0f) * 1.5f, 0.0f), 3.0f);
    int jx0 = min((int)ux0, 2), jy0 = min((int)uy0, 2);
    float tx0 = ux0 - (float)jx0, ty0 = uy0 - (float)jy0;
    float sx0 = 1.0f - tx0, sy0 = 1.0f - ty0;
    const float c00_0 = sx0 * sy0, c01_0 = sx0 * ty0,
                c10_0 = tx0 * sy0, c11_0 = tx0 * ty0;

    // ---- coefficients edge 1 ----
    float ux1 = fminf(fmaxf((a1.x + 1.0f) * 1.5f, 0.0f), 3.0f);
    float uy1 = fminf(fmaxf((a1.y + 1.0f) * 1.5f, 0.0f), 3.0f);
    int jx1 = min((int)ux1, 2), jy1 = min((int)uy1, 2);
    float tx1 = ux1 - (float)jx1, ty1 = uy1 - (float)jy1;
    float sx1 = 1.0f - tx1, sy1 = 1.0f - ty1;
    const float c00_1 = sx1 * sy1, c01_1 = sx1 * ty1,
                c10_1 = tx1 * sy1, c11_1 = tx1 * ty1;

    // ---- issue all 8 corner loads back-to-back (max MLP) ----
    // k = kx*4 + ky ; corner (jx,jy): +32 elems per ky step, +128 per kx step
    const __half* Y0 = &g_Y[(size_t)src0 * YROW + (jx0 * NB + jy0) * F_OUT + c];
    const __half* Y1 = &g_Y[(size_t)(has1 ? src1 : src0) * YROW
                            + (jx1 * NB + jy1) * F_OUT + c];
    Half4 v00_0 = *(const Half4*)(Y0);
    Half4 v01_0 = *(const Half4*)(Y0 + 32);
    Half4 v10_0 = *(const Half4*)(Y0 + 128);
    Half4 v11_0 = *(const Half4*)(Y0 + 160);
    Half4 v00_1 = *(const Half4*)(Y1);
    Half4 v01_1 = *(const Half4*)(Y1 + 32);
    Half4 v10_1 = *(const Half4*)(Y1 + 128);
    Half4 v11_1 = *(const Half4*)(Y1 + 160);

    // ---- edge 0 math + scatter ----
    {
        float2 f00a = __half22float2(v00_0.a), f00b = __half22float2(v00_0.b);
        float2 f01a = __half22float2(v01_0.a), f01b = __half22float2(v01_0.b);
        float2 f10a = __half22float2(v10_0.a), f10b = __half22float2(v10_0.b);
        float2 f11a = __half22float2(v11_0.a), f11b = __half22float2(v11_0.b);
        float r0 = c00_0*f00a.x + c01_0*f01a.x + c10_0*f10a.x + c11_0*f11a.x;
        float r1 = c00_0*f00a.y + c01_0*f01a.y + c10_0*f10a.y + c11_0*f11a.y;
        float r2 = c00_0*f00b.x + c01_0*f01b.x + c10_0*f10b.x + c11_0*f11b.x;
        float r3 = c00_0*f00b.y + c01_0*f01b.y + c10_0*f10b.y + c11_0*f11b.y;
        float* dp = out + dst0 * F_OUT + c;   // 16B-aligned
        asm volatile("red.global.add.v4.f32 [%0], {%1, %2, %3, %4};"
                     :: "l"(dp), "f"(r0), "f"(r1), "f"(r2), "f"(r3)
                     : "memory");
    }

    // ---- edge 1 math + scatter ----
    if (has1) {
        float2 f00a = __half22float2(v00_1.a), f00b = __half22float2(v00_1.b);
        float2 f01a = __half22float2(v01_1.a), f01b = __half22float2(v01_1.b);
        float2 f10a = __half22float2(v10_1.a), f10b = __half22float2(v10_1.b);
        float2 f11a = __half22float2(v11_1.a), f11b = __half22float2(v11_1.b);
        float r0 = c00_1*f00a.x + c01_1*f01a.x + c10_1*f10a.x + c11_1*f11a.x;
        float r1 = c00_1*f00a.y + c01_1*f01a.y + c10_1*f10a.y + c11_1*f11a.y;
        float r2 = c00_1*f00b.x + c01_1*f01b.x + c10_1*f10b.x + c11_1*f11b.x;
        float r3 = c00_1*f00b.y + c01_1*f01b.y + c10_1*f10b.y + c11_1*f11b.y;
        float* dp = out + dst1 * F_OUT + c;   // 16B-aligned
        asm volatile("red.global.add.v4.f32 [%0], {%1, %2, %3, %4};"
                     :: "l"(dp), "f"(r0), "f"(r1), "f"(r2), "f"(r3)
                     : "memory");
    }
}

// ---------------------------------------------------------------------------
// Launch
// Inputs (metadata order): x_i, x_j, edge_index, edge_attr, weight
// ---------------------------------------------------------------------------
extern "C" void kernel_launch(void* const* d_in, const int* in_sizes, int n_in,
                              void* d_out, int out_size)
{
    const float*  x_j = (const float*) d_in[1];
    const int*    ei  = (const int*)   d_in[2];
    const float2* ea  = (const float2*)d_in[3];
    const float*  w   = (const float*) d_in[4];
    float* out = (float*)d_out;

    const int n_nodes = in_sizes[0] / F_IN;
    const int E       = in_sizes[2] / 2;

    // Zero the output via async memset (graph-capturable, 0x00 == 0.0f).
    // Removes the serialized zero-fill prologue from K1.
    cudaMemsetAsync(d_out, 0, (size_t)out_size * sizeof(float));

    // K1: build Y via tensor cores, smem-staged coalesced stores (round-8)
    {
        static const int smem_bytes =
            (512 * WPAD + 8 * 16 * DCOLS) * (int)sizeof(__half);  // ~106 KB
        cudaFuncSetAttribute(build_Y_mma,
                             cudaFuncAttributeMaxDynamicSharedMemorySize, smem_bytes);
        int mtiles = n_nodes >> 4;                 // 3125
        int blocks = (mtiles + 7) / 8;
        if (blocks > 296) blocks = 296;            // 2 blocks/SM, grid-stride
        build_Y_mma<<<blocks, 256, smem_bytes>>>(x_j, w, n_nodes);
    }

    // K2: edge gather + reduction scatter, 2 edges per thread for MLP
    {
        int Ehalf = (E + 1) >> 1;
        long long threads = (long long)Ehalf * 8;
        int blocks = (int)((threads + 255) / 256);
        edge_msg_kernel<<<blocks, 256>>>(ei, ea, out, E, Ehalf);
    }

    (void)n_in; (void)out_size;
}